// round 14
// baseline (speedup 1.0000x reference)
#include <cuda_runtime.h>
#include <cstdint>
#include <math.h>

// ---------------- problem constants ----------------
#define B_    2048
#define POOL  512
#define TOPK  4
#define TOP8  8
#define EPL   8
#define GPL   8
#define EMB   768
#define KEYD  768

// output offsets (float32 elements)
#define PK_ROWS   20
#define PK_SZ     ((size_t)B_ * PK_ROWS * EMB)
#define PV_OFF    (PK_SZ)
#define LOSS_OFF  (2 * PK_SZ)
#define CNT_OFF   (LOSS_OFF + 1)
#define XB_OFF    (CNT_OFF + POOL)   // odd offset -> only 4-byte aligned!

#define GEMM_BLOCKS 256

// ---------------- device scratch ----------------
__device__ float g_C[B_ * POOL];
__device__ float g_invq[B_];
__device__ float g_invk[POOL];
__device__ float g_cpart[32 * POOL];
__device__ int   g_cnt[POOL];
__device__ unsigned int g_ticket;

// ---------------- helpers ----------------
__device__ __forceinline__ void mma_tf32(float* c, const uint32_t* a, const uint32_t* b) {
    asm volatile(
        "mma.sync.aligned.m16n8k8.row.col.f32.tf32.tf32.f32 "
        "{%0,%1,%2,%3}, {%4,%5,%6,%7}, {%8,%9}, {%0,%1,%2,%3};"
        : "+f"(c[0]), "+f"(c[1]), "+f"(c[2]), "+f"(c[3])
        : "r"(a[0]), "r"(a[1]), "r"(a[2]), "r"(a[3]), "r"(b[0]), "r"(b[1]));
}
__device__ __forceinline__ void cpa16(uint32_t dst, const void* src) {
    asm volatile("cp.async.cg.shared.global [%0], [%1], 16;" :: "r"(dst), "l"(src));
}
__device__ __forceinline__ float inv_norm(float ss) {
    return 1.0f / fmaxf(sqrtf(ss), 1e-12f);
}
__device__ __forceinline__ float sq(uint32_t u) {
    float f = __uint_as_float(u);
    return f * f;
}

// ---------------- kernel 1: gemm (blocks 0..255) + static copies (256..2303) -
// gemm: 256 threads, 8 warps 4m x 2n (warp tile 16x32), BM=BN=64, BK=32,
// 2-stage cp.async, fused norms + colsum partials (R10 proven config).
// static blocks: copy G rows + x_block row for batch b = blockIdx.x - 256,
// overlapping with the latency-bound gemm (gemm DRAM = 3.4%).
#define BM 64
#define BN 64
#define BK 32
#define RST 36
#define STAGE_B (64 * RST * 4)
__global__ __launch_bounds__(256) void gemmstatic_kernel(const float* __restrict__ A,
                                                         const float* __restrict__ Bm,
                                                         float* __restrict__ C,
                                                         const float* __restrict__ g_p,
                                                         const float* __restrict__ xb,
                                                         float* __restrict__ out) {
    const int t    = threadIdx.x;
    const int lane = t & 31;
    const int wid  = t >> 5;

    // ---------- static-copy blocks ----------
    if (blockIdx.x >= GEMM_BLOCKS) {
        const int b = blockIdx.x - GEMM_BLOCKS;
        // G rows: warp g -> g_p row g (g<4: Pk rows 16..19; g>=4: Pv rows 16..19)
        {
            const float4* src = (const float4*)(g_p + (size_t)wid * EMB);
            float4* dst = (wid < 4)
                ? (float4*)(out + ((size_t)b * PK_ROWS + 16 + wid) * EMB)
                : (float4*)(out + PV_OFF + ((size_t)b * PK_ROWS + 16 + (wid - 4)) * EMB);
            #pragma unroll
            for (int i = 0; i < 6; i++)
                __stcs(dst + lane + 32 * i, src[lane + 32 * i]);
        }
        // x_block passthrough (dst only 4B-aligned -> scalar streaming stores)
        {
            const float* s = xb + (size_t)b * EMB;
            float* d = out + XB_OFF + (size_t)b * EMB;
            #pragma unroll
            for (int i = 0; i < 3; i++)
                __stcs(d + t + 256 * i, s[t + 256 * i]);
        }
        return;
    }

    // ---------- gemm blocks ----------
    __shared__ __align__(16) uint32_t As[2][BM][RST];
    __shared__ __align__(16) uint32_t Bs[2][BN][RST];
    __shared__ float s_iq[64];
    __shared__ float s_ik[64];
    __shared__ float s_cs[64];

    const int gid  = lane >> 2;
    const int tig  = lane & 3;
    const int wm   = (wid >> 1) * 16;
    const int wn   = (wid & 1) * 32;
    const int bx   = blockIdx.x & 7;       // POOL/BN = 8
    const int by   = blockIdx.x >> 3;      // B_/BM = 32
    const int m0   = by * BM;
    const int n0   = bx * BN;

    if (blockIdx.x == 0) {
        g_cnt[t] = 0; g_cnt[t + 256] = 0;
        if (t == 0) g_ticket = 0u;
    }

    const int arow = t >> 2;
    const int aq   = (t & 3) * 8;
    const float* Aptr = A  + (size_t)(m0 + arow) * KEYD + aq;
    const float* Bptr = Bm + (size_t)(n0 + arow) * KEYD + aq;
    const uint32_t sA = (uint32_t)__cvta_generic_to_shared(&As[0][arow][aq]);
    const uint32_t sB = (uint32_t)__cvta_generic_to_shared(&Bs[0][arow][aq]);

    #define ISSUE(st_, k0_)                                               \
        { cpa16(sA + (st_) * STAGE_B,      Aptr + (k0_));                 \
          cpa16(sA + (st_) * STAGE_B + 16, Aptr + (k0_) + 4);             \
          cpa16(sB + (st_) * STAGE_B,      Bptr + (k0_));                 \
          cpa16(sB + (st_) * STAGE_B + 16, Bptr + (k0_) + 4);             \
          asm volatile("cp.async.commit_group;"); }

    float acc[4][4];
    #pragma unroll
    for (int j = 0; j < 4; j++)
        #pragma unroll
        for (int v = 0; v < 4; v++) acc[j][v] = 0.f;

    float qa0 = 0.f, qa1 = 0.f;
    float qb[4] = {0.f, 0.f, 0.f, 0.f};
    const bool doA = (wid & 1) == 0;
    const bool doB = (wid >> 1) == 0;

    ISSUE(0, 0);

    const int NIT = KEYD / BK;   // 24
    for (int it = 0; it < NIT; it++) {
        asm volatile("cp.async.wait_group 0;");
        __syncthreads();
        if (it + 1 < NIT) ISSUE((it + 1) & 1, (it + 1) * BK);
        const int st = it & 1;
        #pragma unroll
        for (int kk = 0; kk < BK; kk += 8) {
            uint32_t af[4], bf[4][2];
            {
                int mb = wm + gid;
                af[0] = As[st][mb][kk + tig];
                af[1] = As[st][mb + 8][kk + tig];
                af[2] = As[st][mb][kk + tig + 4];
                af[3] = As[st][mb + 8][kk + tig + 4];
            }
            #pragma unroll
            for (int nt = 0; nt < 4; nt++) {
                int nb = wn + nt * 8 + gid;
                bf[nt][0] = Bs[st][nb][kk + tig];
                bf[nt][1] = Bs[st][nb][kk + tig + 4];
            }
            if (doA) { qa0 += sq(af[0]) + sq(af[2]); qa1 += sq(af[1]) + sq(af[3]); }
            if (doB) {
                #pragma unroll
                for (int nt = 0; nt < 4; nt++)
                    qb[nt] += sq(bf[nt][0]) + sq(bf[nt][1]);
            }
            #pragma unroll
            for (int nt = 0; nt < 4; nt++)
                mma_tf32(acc[nt], af, bf[nt]);
        }
        __syncthreads();
    }

    // ---- finalize norms -> SMEM (publish to global on grid edges) ----
    if (doA) {
        float a0 = qa0, a1 = qa1;
        a0 += __shfl_xor_sync(0xffffffffu, a0, 1);
        a0 += __shfl_xor_sync(0xffffffffu, a0, 2);
        a1 += __shfl_xor_sync(0xffffffffu, a1, 1);
        a1 += __shfl_xor_sync(0xffffffffu, a1, 2);
        if (tig == 0) {
            s_iq[wm + gid]     = inv_norm(a0);
            s_iq[wm + 8 + gid] = inv_norm(a1);
        }
    }
    if (doB) {
        #pragma unroll
        for (int nt = 0; nt < 4; nt++) {
            float b0 = qb[nt];
            b0 += __shfl_xor_sync(0xffffffffu, b0, 1);
            b0 += __shfl_xor_sync(0xffffffffu, b0, 2);
            if (tig == 0) s_ik[wn + nt * 8 + gid] = inv_norm(b0);
        }
    }
    if (t < 64) s_cs[t] = 0.f;
    __syncthreads();

    if (bx == 0 && t < 64) g_invq[m0 + t] = s_iq[t];
    if (by == 0 && t < 64) g_invk[n0 + t] = s_ik[t];

    // ---- epilogue: scale, store C, column-sum partials ----
    float cs0[4], cs1[4];
    {
        int ml = wm + gid;
        float iq0 = s_iq[ml], iq1 = s_iq[ml + 8];
        int m = m0 + ml;
        #pragma unroll
        for (int nt = 0; nt < 4; nt++) {
            int nl = wn + nt * 8 + 2 * tig;
            int n  = n0 + nl;
            float ik0 = s_ik[nl], ik1 = s_ik[nl + 1];
            float v0 = acc[nt][0] * iq0 * ik0;
            float v1 = acc[nt][1] * iq0 * ik1;
            float v2 = acc[nt][2] * iq1 * ik0;
            float v3 = acc[nt][3] * iq1 * ik1;
            C[(size_t)m * POOL + n]           = v0;
            C[(size_t)m * POOL + n + 1]       = v1;
            C[(size_t)(m + 8) * POOL + n]     = v2;
            C[(size_t)(m + 8) * POOL + n + 1] = v3;
            cs0[nt] = v0 + v2;
            cs1[nt] = v1 + v3;
        }
    }
    #pragma unroll
    for (int nt = 0; nt < 4; nt++) {
        float c0 = cs0[nt], c1 = cs1[nt];
        #pragma unroll
        for (int off = 4; off < 32; off <<= 1) {
            c0 += __shfl_xor_sync(0xffffffffu, c0, off);
            c1 += __shfl_xor_sync(0xffffffffu, c1, off);
        }
        if (gid == 0) {
            int nl = wn + nt * 8 + 2 * tig;
            atomicAdd(&s_cs[nl], c0);
            atomicAdd(&s_cs[nl + 1], c1);
        }
    }
    __syncthreads();
    if (t < 64) g_cpart[by * POOL + n0 + t] = s_cs[t];
}

// ---------------- kernel 2: fused route + E-row gather + ticket finish ------
// Block `row`: top-8 scan (warp0) -> 8-warp exact fp32 recheck -> top-4 ->
// stream 32 rows (16 Pk + 16 Pv). Last block (ticket) writes counts + loss.
__global__ __launch_bounds__(256) void routegather_kernel(const float* __restrict__ C,
                                                          const float* __restrict__ xq,
                                                          const float* __restrict__ ek,
                                                          const float* __restrict__ e_p,
                                                          float* __restrict__ out) {
    const int row  = blockIdx.x;
    const int t    = threadIdx.x;
    const int lane = t & 31;
    const int w    = t >> 5;
    __shared__ int   s_cand[TOP8];
    __shared__ float s_ex[TOP8];
    __shared__ int   s_sel[TOPK];
    __shared__ bool  s_last;

    if (w == 0) {
        const float* crow = C + (size_t)row * POOL;
        float d[16];
        #pragma unroll
        for (int u = 0; u < 16; u++) d[u] = 1.0f - crow[u * 32 + lane];
        #pragma unroll
        for (int k = 0; k < TOP8; k++) {
            float best = INFINITY; int bi = 0x7fffffff;
            #pragma unroll
            for (int u = 0; u < 16; u++) {
                int p = u * 32 + lane;
                if (d[u] < best || (d[u] == best && p < bi)) { best = d[u]; bi = p; }
            }
            #pragma unroll
            for (int off = 16; off; off >>= 1) {
                float ov = __shfl_xor_sync(0xffffffffu, best, off);
                int   oi = __shfl_xor_sync(0xffffffffu, bi, off);
                if (ov < best || (ov == best && oi < bi)) { best = ov; bi = oi; }
            }
            if (lane == 0) s_cand[k] = bi;
            int ul = bi >> 5, ll = bi & 31;
            #pragma unroll
            for (int u = 0; u < 16; u++)
                if (u == ul && ll == lane) d[u] = INFINITY;
        }
    }
    __syncthreads();

    // exact fp32 recheck: warp w -> candidate w
    {
        int p = s_cand[w];
        const float4* q4 = (const float4*)(xq + (size_t)row * KEYD);
        const float4* k4 = (const float4*)(ek + (size_t)p * KEYD);
        float s = 0.f;
        #pragma unroll
        for (int i = 0; i < 6; i++) {
            float4 qv = q4[lane + 32 * i];
            float4 kv = k4[lane + 32 * i];
            s += qv.x * kv.x + qv.y * kv.y + qv.z * kv.z + qv.w * kv.w;
        }
        #pragma unroll
        for (int off = 16; off; off >>= 1) s += __shfl_xor_sync(0xffffffffu, s, off);
        if (lane == 0) s_ex[w] = 1.0f - s * g_invq[row] * g_invk[p];
    }
    __syncthreads();

    if (t == 0) {
        bool used[TOP8];
        #pragma unroll
        for (int c = 0; c < TOP8; c++) used[c] = false;
        #pragma unroll
        for (int k = 0; k < TOPK; k++) {
            float best = INFINITY; int bi = 0x7fffffff; int slot = 0;
            #pragma unroll
            for (int c = 0; c < TOP8; c++) {
                if (!used[c] && (s_ex[c] < best || (s_ex[c] == best && s_cand[c] < bi))) {
                    best = s_ex[c]; bi = s_cand[c]; slot = c;
                }
            }
            used[slot] = true;
            s_sel[k] = bi;
            atomicAdd(&g_cnt[bi], 1);
        }
    }
    __syncthreads();

    // gather: 32 row-copies (16 Pk + 16 Pv), warp w does copies w, w+8, w+16, w+24
    int p0 = s_sel[0], p1 = s_sel[1], p2 = s_sel[2], p3 = s_sel[3];
    #pragma unroll
    for (int j = 0; j < 4; j++) {
        int c = w + 8 * j;               // 0..31
        int isv = c >> 4;                // 0 = Pk, 1 = Pv
        int rr4 = c & 15;                // dest row 0..15
        int k   = rr4 >> 2;
        int rr  = rr4 & 3;
        int p   = (k == 0) ? p0 : (k == 1) ? p1 : (k == 2) ? p2 : p3;
        const float4* src = (const float4*)(e_p + ((size_t)p * EPL + isv * 4 + rr) * EMB);
        float4* dst = (float4*)(out + (size_t)isv * PV_OFF
                                + ((size_t)row * PK_ROWS + rr4) * EMB);
        #pragma unroll
        for (int i = 0; i < 6; i++)
            __stcs(dst + lane + 32 * i, src[lane + 32 * i]);
    }

    // ---- last block writes counts + loss ----
    if (t == 0) {
        __threadfence();
        unsigned int old = atomicAdd(&g_ticket, 1u);
        s_last = (old == (unsigned int)(B_ - 1));
    }
    __syncthreads();
    if (s_last) {
        __shared__ float s_w[8];
        float local = 0.f;
        #pragma unroll
        for (int rep = 0; rep < 2; rep++) {
            int p = t + rep * 256;
            int c = *(volatile int*)&g_cnt[p];
            out[CNT_OFF + p] = (float)c;
            float colsum = 0.f;
            #pragma unroll
            for (int by = 0; by < 32; by++) colsum += g_cpart[by * POOL + p];
            local += colsum * (float)c;
        }
        #pragma unroll
        for (int off = 16; off; off >>= 1)
            local += __shfl_xor_sync(0xffffffffu, local, off);
        if (lane == 0) s_w[w] = local;
        __syncthreads();
        if (t == 0) {
            float tot = 0.f;
            #pragma unroll
            for (int i = 0; i < 8; i++) tot += s_w[i];
            out[LOSS_OFF] = 1.0f - tot / ((float)B_ * (float)B_ * (float)TOPK);
        }
    }
}

// ---------------- launch ----------------
extern "C" void kernel_launch(void* const* d_in, const int* in_sizes, int n_in,
                              void* d_out, int out_size) {
    const float* x_querry = (const float*)d_in[0];
    const float* x_block  = (const float*)d_in[1];
    const float* e_k      = (const float*)d_in[2];
    const float* e_p      = (const float*)d_in[3];
    const float* g_p      = (const float*)d_in[4];
    (void)in_sizes; (void)n_in; (void)out_size;

    float* out = (float*)d_out;
    float* d_C = nullptr;
    cudaGetSymbolAddress((void**)&d_C, g_C);

    gemmstatic_kernel<<<GEMM_BLOCKS + B_, 256>>>(x_querry, e_k, d_C,
                                                 g_p, x_block, out);       // 1
    routegather_kernel<<<B_, 256>>>(d_C, x_querry, e_k, e_p, out);         // 2
}

// round 15
// speedup vs baseline: 1.0559x; 1.0559x over previous
#include <cuda_runtime.h>
#include <cstdint>
#include <math.h>

// ---------------- problem constants ----------------
#define B_    2048
#define POOL  512
#define TOPK  4
#define TOP8  8
#define EPL   8
#define GPL   8
#define EMB   768
#define KEYD  768

// output offsets (float32 elements)
#define PK_ROWS   20
#define PK_SZ     ((size_t)B_ * PK_ROWS * EMB)
#define PV_OFF    (PK_SZ)
#define LOSS_OFF  (2 * PK_SZ)
#define CNT_OFF   (LOSS_OFF + 1)
#define XB_OFF    (CNT_OFF + POOL)   // odd offset -> only 4-byte aligned!

#define GEMM_BLOCKS 256

// ---------------- device scratch ----------------
__device__ float g_C[B_ * POOL];
__device__ float g_invq[B_];
__device__ float g_invk[POOL];
__device__ float g_cpart[32 * POOL];
__device__ int   g_cnt[POOL];

// ---------------- helpers ----------------
__device__ __forceinline__ void mma_tf32(float* c, const uint32_t* a, const uint32_t* b) {
    asm volatile(
        "mma.sync.aligned.m16n8k8.row.col.f32.tf32.tf32.f32 "
        "{%0,%1,%2,%3}, {%4,%5,%6,%7}, {%8,%9}, {%0,%1,%2,%3};"
        : "+f"(c[0]), "+f"(c[1]), "+f"(c[2]), "+f"(c[3])
        : "r"(a[0]), "r"(a[1]), "r"(a[2]), "r"(a[3]), "r"(b[0]), "r"(b[1]));
}
__device__ __forceinline__ void cpa16(uint32_t dst, const void* src) {
    asm volatile("cp.async.cg.shared.global [%0], [%1], 16;" :: "r"(dst), "l"(src));
}
__device__ __forceinline__ float inv_norm(float ss) {
    return 1.0f / fmaxf(sqrtf(ss), 1e-12f);
}
__device__ __forceinline__ float sq(uint32_t u) {
    float f = __uint_as_float(u);
    return f * f;
}

// ---------------- kernel 1: gemm (blocks 0..255) + static copies (256..2303) -
// gemm: 256 threads, 8 warps 4m x 2n (warp tile 16x32), BM=BN=64, BK=32,
// 2-stage cp.async, fused norms + colsum partials.
// static blocks: copy G rows + x_block row, overlapping the latency-bound gemm.
// Measured R14: ~30us total (static absorbed for ~1us).
#define BM 64
#define BN 64
#define BK 32
#define RST 36
#define STAGE_B (64 * RST * 4)
__global__ __launch_bounds__(256) void gemmstatic_kernel(const float* __restrict__ A,
                                                         const float* __restrict__ Bm,
                                                         float* __restrict__ C,
                                                         const float* __restrict__ g_p,
                                                         const float* __restrict__ xb,
                                                         float* __restrict__ out) {
    const int t    = threadIdx.x;
    const int lane = t & 31;
    const int wid  = t >> 5;

    // ---------- static-copy blocks ----------
    if (blockIdx.x >= GEMM_BLOCKS) {
        const int b = blockIdx.x - GEMM_BLOCKS;
        {
            const float4* src = (const float4*)(g_p + (size_t)wid * EMB);
            float4* dst = (wid < 4)
                ? (float4*)(out + ((size_t)b * PK_ROWS + 16 + wid) * EMB)
                : (float4*)(out + PV_OFF + ((size_t)b * PK_ROWS + 16 + (wid - 4)) * EMB);
            #pragma unroll
            for (int i = 0; i < 6; i++)
                __stcs(dst + lane + 32 * i, src[lane + 32 * i]);
        }
        {
            const float* s = xb + (size_t)b * EMB;
            float* d = out + XB_OFF + (size_t)b * EMB;
            #pragma unroll
            for (int i = 0; i < 3; i++)
                __stcs(d + t + 256 * i, s[t + 256 * i]);
        }
        return;
    }

    // ---------- gemm blocks ----------
    __shared__ __align__(16) uint32_t As[2][BM][RST];
    __shared__ __align__(16) uint32_t Bs[2][BN][RST];
    __shared__ float s_iq[64];
    __shared__ float s_ik[64];
    __shared__ float s_cs[64];

    const int gid  = lane >> 2;
    const int tig  = lane & 3;
    const int wm   = (wid >> 1) * 16;
    const int wn   = (wid & 1) * 32;
    const int bx   = blockIdx.x & 7;       // POOL/BN = 8
    const int by   = blockIdx.x >> 3;      // B_/BM = 32
    const int m0   = by * BM;
    const int n0   = bx * BN;

    if (blockIdx.x == 0) {
        g_cnt[t] = 0; g_cnt[t + 256] = 0;
    }

    const int arow = t >> 2;
    const int aq   = (t & 3) * 8;
    const float* Aptr = A  + (size_t)(m0 + arow) * KEYD + aq;
    const float* Bptr = Bm + (size_t)(n0 + arow) * KEYD + aq;
    const uint32_t sA = (uint32_t)__cvta_generic_to_shared(&As[0][arow][aq]);
    const uint32_t sB = (uint32_t)__cvta_generic_to_shared(&Bs[0][arow][aq]);

    #define ISSUE(st_, k0_)                                               \
        { cpa16(sA + (st_) * STAGE_B,      Aptr + (k0_));                 \
          cpa16(sA + (st_) * STAGE_B + 16, Aptr + (k0_) + 4);             \
          cpa16(sB + (st_) * STAGE_B,      Bptr + (k0_));                 \
          cpa16(sB + (st_) * STAGE_B + 16, Bptr + (k0_) + 4);             \
          asm volatile("cp.async.commit_group;"); }

    float acc[4][4];
    #pragma unroll
    for (int j = 0; j < 4; j++)
        #pragma unroll
        for (int v = 0; v < 4; v++) acc[j][v] = 0.f;

    float qa0 = 0.f, qa1 = 0.f;
    float qb[4] = {0.f, 0.f, 0.f, 0.f};
    const bool doA = (wid & 1) == 0;
    const bool doB = (wid >> 1) == 0;

    ISSUE(0, 0);

    const int NIT = KEYD / BK;   // 24
    for (int it = 0; it < NIT; it++) {
        asm volatile("cp.async.wait_group 0;");
        __syncthreads();
        if (it + 1 < NIT) ISSUE((it + 1) & 1, (it + 1) * BK);
        const int st = it & 1;
        #pragma unroll
        for (int kk = 0; kk < BK; kk += 8) {
            uint32_t af[4], bf[4][2];
            {
                int mb = wm + gid;
                af[0] = As[st][mb][kk + tig];
                af[1] = As[st][mb + 8][kk + tig];
                af[2] = As[st][mb][kk + tig + 4];
                af[3] = As[st][mb + 8][kk + tig + 4];
            }
            #pragma unroll
            for (int nt = 0; nt < 4; nt++) {
                int nb = wn + nt * 8 + gid;
                bf[nt][0] = Bs[st][nb][kk + tig];
                bf[nt][1] = Bs[st][nb][kk + tig + 4];
            }
            if (doA) { qa0 += sq(af[0]) + sq(af[2]); qa1 += sq(af[1]) + sq(af[3]); }
            if (doB) {
                #pragma unroll
                for (int nt = 0; nt < 4; nt++)
                    qb[nt] += sq(bf[nt][0]) + sq(bf[nt][1]);
            }
            #pragma unroll
            for (int nt = 0; nt < 4; nt++)
                mma_tf32(acc[nt], af, bf[nt]);
        }
        __syncthreads();
    }

    // ---- finalize norms -> SMEM (publish to global on grid edges) ----
    if (doA) {
        float a0 = qa0, a1 = qa1;
        a0 += __shfl_xor_sync(0xffffffffu, a0, 1);
        a0 += __shfl_xor_sync(0xffffffffu, a0, 2);
        a1 += __shfl_xor_sync(0xffffffffu, a1, 1);
        a1 += __shfl_xor_sync(0xffffffffu, a1, 2);
        if (tig == 0) {
            s_iq[wm + gid]     = inv_norm(a0);
            s_iq[wm + 8 + gid] = inv_norm(a1);
        }
    }
    if (doB) {
        #pragma unroll
        for (int nt = 0; nt < 4; nt++) {
            float b0 = qb[nt];
            b0 += __shfl_xor_sync(0xffffffffu, b0, 1);
            b0 += __shfl_xor_sync(0xffffffffu, b0, 2);
            if (tig == 0) s_ik[wn + nt * 8 + gid] = inv_norm(b0);
        }
    }
    if (t < 64) s_cs[t] = 0.f;
    __syncthreads();

    if (bx == 0 && t < 64) g_invq[m0 + t] = s_iq[t];
    if (by == 0 && t < 64) g_invk[n0 + t] = s_ik[t];

    // ---- epilogue: scale, store C, column-sum partials ----
    float cs0[4], cs1[4];
    {
        int ml = wm + gid;
        float iq0 = s_iq[ml], iq1 = s_iq[ml + 8];
        int m = m0 + ml;
        #pragma unroll
        for (int nt = 0; nt < 4; nt++) {
            int nl = wn + nt * 8 + 2 * tig;
            int n  = n0 + nl;
            float ik0 = s_ik[nl], ik1 = s_ik[nl + 1];
            float v0 = acc[nt][0] * iq0 * ik0;
            float v1 = acc[nt][1] * iq0 * ik1;
            float v2 = acc[nt][2] * iq1 * ik0;
            float v3 = acc[nt][3] * iq1 * ik1;
            C[(size_t)m * POOL + n]           = v0;
            C[(size_t)m * POOL + n + 1]       = v1;
            C[(size_t)(m + 8) * POOL + n]     = v2;
            C[(size_t)(m + 8) * POOL + n + 1] = v3;
            cs0[nt] = v0 + v2;
            cs1[nt] = v1 + v3;
        }
    }
    #pragma unroll
    for (int nt = 0; nt < 4; nt++) {
        float c0 = cs0[nt], c1 = cs1[nt];
        #pragma unroll
        for (int off = 4; off < 32; off <<= 1) {
            c0 += __shfl_xor_sync(0xffffffffu, c0, off);
            c1 += __shfl_xor_sync(0xffffffffu, c1, off);
        }
        if (gid == 0) {
            int nl = wn + nt * 8 + 2 * tig;
            atomicAdd(&s_cs[nl], c0);
            atomicAdd(&s_cs[nl + 1], c1);
        }
    }
    __syncthreads();
    if (t < 64) g_cpart[by * POOL + n0 + t] = s_cs[t];
}

// ---------------- kernel 2: fused route + E-row gather (NO threadfence) -----
// Block `row`: top-8 scan (warp0) -> 8-warp exact fp32 recheck -> top-4 ->
// stream 32 rows (16 Pk + 16 Pv). Blocks retire freely (no store-drain wait).
__global__ __launch_bounds__(256) void routegather_kernel(const float* __restrict__ C,
                                                          const float* __restrict__ xq,
                                                          const float* __restrict__ ek,
                                                          const float* __restrict__ e_p,
                                                          float* __restrict__ out) {
    const int row  = blockIdx.x;
    const int t    = threadIdx.x;
    const int lane = t & 31;
    const int w    = t >> 5;
    __shared__ int   s_cand[TOP8];
    __shared__ float s_ex[TOP8];
    __shared__ int   s_sel[TOPK];

    if (w == 0) {
        const float* crow = C + (size_t)row * POOL;
        float d[16];
        #pragma unroll
        for (int u = 0; u < 16; u++) d[u] = 1.0f - crow[u * 32 + lane];
        #pragma unroll
        for (int k = 0; k < TOP8; k++) {
            float best = INFINITY; int bi = 0x7fffffff;
            #pragma unroll
            for (int u = 0; u < 16; u++) {
                int p = u * 32 + lane;
                if (d[u] < best || (d[u] == best && p < bi)) { best = d[u]; bi = p; }
            }
            #pragma unroll
            for (int off = 16; off; off >>= 1) {
                float ov = __shfl_xor_sync(0xffffffffu, best, off);
                int   oi = __shfl_xor_sync(0xffffffffu, bi, off);
                if (ov < best || (ov == best && oi < bi)) { best = ov; bi = oi; }
            }
            if (lane == 0) s_cand[k] = bi;
            int ul = bi >> 5, ll = bi & 31;
            #pragma unroll
            for (int u = 0; u < 16; u++)
                if (u == ul && ll == lane) d[u] = INFINITY;
        }
    }
    __syncthreads();

    // exact fp32 recheck: warp w -> candidate w
    {
        int p = s_cand[w];
        const float4* q4 = (const float4*)(xq + (size_t)row * KEYD);
        const float4* k4 = (const float4*)(ek + (size_t)p * KEYD);
        float s = 0.f;
        #pragma unroll
        for (int i = 0; i < 6; i++) {
            float4 qv = q4[lane + 32 * i];
            float4 kv = k4[lane + 32 * i];
            s += qv.x * kv.x + qv.y * kv.y + qv.z * kv.z + qv.w * kv.w;
        }
        #pragma unroll
        for (int off = 16; off; off >>= 1) s += __shfl_xor_sync(0xffffffffu, s, off);
        if (lane == 0) s_ex[w] = 1.0f - s * g_invq[row] * g_invk[p];
    }
    __syncthreads();

    if (t == 0) {
        bool used[TOP8];
        #pragma unroll
        for (int c = 0; c < TOP8; c++) used[c] = false;
        #pragma unroll
        for (int k = 0; k < TOPK; k++) {
            float best = INFINITY; int bi = 0x7fffffff; int slot = 0;
            #pragma unroll
            for (int c = 0; c < TOP8; c++) {
                if (!used[c] && (s_ex[c] < best || (s_ex[c] == best && s_cand[c] < bi))) {
                    best = s_ex[c]; bi = s_cand[c]; slot = c;
                }
            }
            used[slot] = true;
            s_sel[k] = bi;
            atomicAdd(&g_cnt[bi], 1);
        }
    }
    __syncthreads();

    // gather: 32 row-copies (16 Pk + 16 Pv), warp w does copies w, w+8, w+16, w+24
    int p0 = s_sel[0], p1 = s_sel[1], p2 = s_sel[2], p3 = s_sel[3];
    #pragma unroll
    for (int j = 0; j < 4; j++) {
        int c = w + 8 * j;               // 0..31
        int isv = c >> 4;                // 0 = Pk, 1 = Pv
        int rr4 = c & 15;                // dest row 0..15
        int k   = rr4 >> 2;
        int rr  = rr4 & 3;
        int p   = (k == 0) ? p0 : (k == 1) ? p1 : (k == 2) ? p2 : p3;
        const float4* src = (const float4*)(e_p + ((size_t)p * EPL + isv * 4 + rr) * EMB);
        float4* dst = (float4*)(out + (size_t)isv * PV_OFF
                                + ((size_t)row * PK_ROWS + rr4) * EMB);
        #pragma unroll
        for (int i = 0; i < 6; i++)
            __stcs(dst + lane + 32 * i, src[lane + 32 * i]);
    }
}

// ---------------- kernel 3: finish (counts + loss), 1 block ----------------
__global__ __launch_bounds__(512) void finish_kernel(float* __restrict__ out) {
    const int p = threadIdx.x;
    const int lane = p & 31;
    int c = g_cnt[p];
    out[CNT_OFF + p] = (float)c;
    float colsum = 0.f;
    #pragma unroll
    for (int by = 0; by < 32; by++) colsum += g_cpart[by * POOL + p];
    float local = colsum * (float)c;
    #pragma unroll
    for (int off = 16; off; off >>= 1)
        local += __shfl_xor_sync(0xffffffffu, local, off);
    __shared__ float s_w[16];
    if (lane == 0) s_w[p >> 5] = local;
    __syncthreads();
    if (p == 0) {
        float tot = 0.f;
        #pragma unroll
        for (int i = 0; i < 16; i++) tot += s_w[i];
        out[LOSS_OFF] = 1.0f - tot / ((float)B_ * (float)B_ * (float)TOPK);
    }
}

// ---------------- launch ----------------
extern "C" void kernel_launch(void* const* d_in, const int* in_sizes, int n_in,
                              void* d_out, int out_size) {
    const float* x_querry = (const float*)d_in[0];
    const float* x_block  = (const float*)d_in[1];
    const float* e_k      = (const float*)d_in[2];
    const float* e_p      = (const float*)d_in[3];
    const float* g_p      = (const float*)d_in[4];
    (void)in_sizes; (void)n_in; (void)out_size;

    float* out = (float*)d_out;
    float* d_C = nullptr;
    cudaGetSymbolAddress((void**)&d_C, g_C);

    gemmstatic_kernel<<<GEMM_BLOCKS + B_, 256>>>(x_querry, e_k, d_C,
                                                 g_p, x_block, out);       // 1
    routegather_kernel<<<B_, 256>>>(d_C, x_querry, e_k, e_p, out);         // 2
    finish_kernel<<<1, 512>>>(out);                                        // 3
}

// round 16
// speedup vs baseline: 1.1054x; 1.0469x over previous
#include <cuda_runtime.h>
#include <cstdint>
#include <math.h>

// ---------------- problem constants ----------------
#define B_    2048
#define POOL  512
#define TOPK  4
#define TOP8  8
#define EPL   8
#define GPL   8
#define EMB   768
#define KEYD  768

// output offsets (float32 elements)
#define PK_ROWS   20
#define PK_SZ     ((size_t)B_ * PK_ROWS * EMB)
#define PV_OFF    (PK_SZ)
#define LOSS_OFF  (2 * PK_SZ)
#define CNT_OFF   (LOSS_OFF + 1)
#define XB_OFF    (CNT_OFF + POOL)   // odd offset -> only 4-byte aligned!

// ---------------- device scratch ----------------
__device__ float g_C[B_ * POOL];
__device__ float g_invq[B_];
__device__ float g_invk[POOL];
__device__ float g_cpart[32 * POOL];
__device__ int   g_cnt[POOL];

// ---------------- helpers ----------------
__device__ __forceinline__ void mma_tf32(float* c, const uint32_t* a, const uint32_t* b) {
    asm volatile(
        "mma.sync.aligned.m16n8k8.row.col.f32.tf32.tf32.f32 "
        "{%0,%1,%2,%3}, {%4,%5,%6,%7}, {%8,%9}, {%0,%1,%2,%3};"
        : "+f"(c[0]), "+f"(c[1]), "+f"(c[2]), "+f"(c[3])
        : "r"(a[0]), "r"(a[1]), "r"(a[2]), "r"(a[3]), "r"(b[0]), "r"(b[1]));
}
__device__ __forceinline__ void cpa16(uint32_t dst, const void* src) {
    asm volatile("cp.async.cg.shared.global [%0], [%1], 16;" :: "r"(dst), "l"(src));
}
__device__ __forceinline__ float inv_norm(float ss) {
    return 1.0f / fmaxf(sqrtf(ss), 1e-12f);
}
__device__ __forceinline__ float sq(uint32_t u) {
    float f = __uint_as_float(u);
    return f * f;
}

// ---------------- kernel 1: tf32 GEMM + fused norms + colsum partials -------
// R10 proven config: 256 threads, 8 warps 4m x 2n (warp tile 16x32),
// BM=BN=64, BK=32, 2-stage cp.async. Measured 29us.
#define BM 64
#define BN 64
#define BK 32
#define RST 36
#define STAGE_B (64 * RST * 4)
__global__ __launch_bounds__(256) void gemm_tf32_kernel(const float* __restrict__ A,
                                                        const float* __restrict__ Bm,
                                                        float* __restrict__ C) {
    __shared__ __align__(16) uint32_t As[2][BM][RST];
    __shared__ __align__(16) uint32_t Bs[2][BN][RST];
    __shared__ float s_iq[64];
    __shared__ float s_ik[64];
    __shared__ float s_cs[64];

    const int t    = threadIdx.x;
    const int lane = t & 31;
    const int wid  = t >> 5;
    const int gid  = lane >> 2;
    const int tig  = lane & 3;
    const int wm   = (wid >> 1) * 16;
    const int wn   = (wid & 1) * 32;
    const int bx   = blockIdx.x;           // 0..7
    const int by   = blockIdx.y;           // 0..31
    const int m0   = by * BM;
    const int n0   = bx * BN;

    if (bx == 0 && by == 0) {
        g_cnt[t] = 0; g_cnt[t + 256] = 0;
    }

    const int arow = t >> 2;
    const int aq   = (t & 3) * 8;
    const float* Aptr = A  + (size_t)(m0 + arow) * KEYD + aq;
    const float* Bptr = Bm + (size_t)(n0 + arow) * KEYD + aq;
    const uint32_t sA = (uint32_t)__cvta_generic_to_shared(&As[0][arow][aq]);
    const uint32_t sB = (uint32_t)__cvta_generic_to_shared(&Bs[0][arow][aq]);

    #define ISSUE(st_, k0_)                                               \
        { cpa16(sA + (st_) * STAGE_B,      Aptr + (k0_));                 \
          cpa16(sA + (st_) * STAGE_B + 16, Aptr + (k0_) + 4);             \
          cpa16(sB + (st_) * STAGE_B,      Bptr + (k0_));                 \
          cpa16(sB + (st_) * STAGE_B + 16, Bptr + (k0_) + 4);             \
          asm volatile("cp.async.commit_group;"); }

    float acc[4][4];
    #pragma unroll
    for (int j = 0; j < 4; j++)
        #pragma unroll
        for (int v = 0; v < 4; v++) acc[j][v] = 0.f;

    float qa0 = 0.f, qa1 = 0.f;
    float qb[4] = {0.f, 0.f, 0.f, 0.f};
    const bool doA = (wid & 1) == 0;
    const bool doB = (wid >> 1) == 0;

    ISSUE(0, 0);

    const int NIT = KEYD / BK;   // 24
    for (int it = 0; it < NIT; it++) {
        asm volatile("cp.async.wait_group 0;");
        __syncthreads();
        if (it + 1 < NIT) ISSUE((it + 1) & 1, (it + 1) * BK);
        const int st = it & 1;
        #pragma unroll
        for (int kk = 0; kk < BK; kk += 8) {
            uint32_t af[4], bf[4][2];
            {
                int mb = wm + gid;
                af[0] = As[st][mb][kk + tig];
                af[1] = As[st][mb + 8][kk + tig];
                af[2] = As[st][mb][kk + tig + 4];
                af[3] = As[st][mb + 8][kk + tig + 4];
            }
            #pragma unroll
            for (int nt = 0; nt < 4; nt++) {
                int nb = wn + nt * 8 + gid;
                bf[nt][0] = Bs[st][nb][kk + tig];
                bf[nt][1] = Bs[st][nb][kk + tig + 4];
            }
            if (doA) { qa0 += sq(af[0]) + sq(af[2]); qa1 += sq(af[1]) + sq(af[3]); }
            if (doB) {
                #pragma unroll
                for (int nt = 0; nt < 4; nt++)
                    qb[nt] += sq(bf[nt][0]) + sq(bf[nt][1]);
            }
            #pragma unroll
            for (int nt = 0; nt < 4; nt++)
                mma_tf32(acc[nt], af, bf[nt]);
        }
        __syncthreads();
    }

    // ---- finalize norms -> SMEM (publish to global on grid edges) ----
    if (doA) {
        float a0 = qa0, a1 = qa1;
        a0 += __shfl_xor_sync(0xffffffffu, a0, 1);
        a0 += __shfl_xor_sync(0xffffffffu, a0, 2);
        a1 += __shfl_xor_sync(0xffffffffu, a1, 1);
        a1 += __shfl_xor_sync(0xffffffffu, a1, 2);
        if (tig == 0) {
            s_iq[wm + gid]     = inv_norm(a0);
            s_iq[wm + 8 + gid] = inv_norm(a1);
        }
    }
    if (doB) {
        #pragma unroll
        for (int nt = 0; nt < 4; nt++) {
            float b0 = qb[nt];
            b0 += __shfl_xor_sync(0xffffffffu, b0, 1);
            b0 += __shfl_xor_sync(0xffffffffu, b0, 2);
            if (tig == 0) s_ik[wn + nt * 8 + gid] = inv_norm(b0);
        }
    }
    if (t < 64) s_cs[t] = 0.f;
    __syncthreads();

    if (bx == 0 && t < 64) g_invq[m0 + t] = s_iq[t];
    if (by == 0 && t < 64) g_invk[n0 + t] = s_ik[t];

    // ---- epilogue: scale, store C, column-sum partials ----
    float cs0[4], cs1[4];
    {
        int ml = wm + gid;
        float iq0 = s_iq[ml], iq1 = s_iq[ml + 8];
        int m = m0 + ml;
        #pragma unroll
        for (int nt = 0; nt < 4; nt++) {
            int nl = wn + nt * 8 + 2 * tig;
            int n  = n0 + nl;
            float ik0 = s_ik[nl], ik1 = s_ik[nl + 1];
            float v0 = acc[nt][0] * iq0 * ik0;
            float v1 = acc[nt][1] * iq0 * ik1;
            float v2 = acc[nt][2] * iq1 * ik0;
            float v3 = acc[nt][3] * iq1 * ik1;
            C[(size_t)m * POOL + n]           = v0;
            C[(size_t)m * POOL + n + 1]       = v1;
            C[(size_t)(m + 8) * POOL + n]     = v2;
            C[(size_t)(m + 8) * POOL + n + 1] = v3;
            cs0[nt] = v0 + v2;
            cs1[nt] = v1 + v3;
        }
    }
    #pragma unroll
    for (int nt = 0; nt < 4; nt++) {
        float c0 = cs0[nt], c1 = cs1[nt];
        #pragma unroll
        for (int off = 4; off < 32; off <<= 1) {
            c0 += __shfl_xor_sync(0xffffffffu, c0, off);
            c1 += __shfl_xor_sync(0xffffffffu, c1, off);
        }
        if (gid == 0) {
            int nl = wn + nt * 8 + 2 * tig;
            atomicAdd(&s_cs[nl], c0);
            atomicAdd(&s_cs[nl + 1], c1);
        }
    }
    __syncthreads();
    if (t < 64) g_cpart[by * POOL + n0 + t] = s_cs[t];
}

// ---------------- kernel 2: mega routegather (NO fence/ticket) --------------
// Block `row`: route -> write ALL 20 Pk + 20 Pv rows (E + G) + x_block row.
// R9's proven write pattern minus the retire-blocking ticket.
__global__ __launch_bounds__(256) void routegather_kernel(const float* __restrict__ C,
                                                          const float* __restrict__ xq,
                                                          const float* __restrict__ ek,
                                                          const float* __restrict__ e_p,
                                                          const float* __restrict__ g_p,
                                                          const float* __restrict__ xb,
                                                          float* __restrict__ out) {
    const int row  = blockIdx.x;
    const int t    = threadIdx.x;
    const int lane = t & 31;
    const int w    = t >> 5;
    __shared__ int   s_cand[TOP8];
    __shared__ float s_ex[TOP8];
    __shared__ int   s_sel[TOPK];

    if (w == 0) {
        const float* crow = C + (size_t)row * POOL;
        float d[16];
        #pragma unroll
        for (int u = 0; u < 16; u++) d[u] = 1.0f - crow[u * 32 + lane];
        #pragma unroll
        for (int k = 0; k < TOP8; k++) {
            float best = INFINITY; int bi = 0x7fffffff;
            #pragma unroll
            for (int u = 0; u < 16; u++) {
                int p = u * 32 + lane;
                if (d[u] < best || (d[u] == best && p < bi)) { best = d[u]; bi = p; }
            }
            #pragma unroll
            for (int off = 16; off; off >>= 1) {
                float ov = __shfl_xor_sync(0xffffffffu, best, off);
                int   oi = __shfl_xor_sync(0xffffffffu, bi, off);
                if (ov < best || (ov == best && oi < bi)) { best = ov; bi = oi; }
            }
            if (lane == 0) s_cand[k] = bi;
            int ul = bi >> 5, ll = bi & 31;
            #pragma unroll
            for (int u = 0; u < 16; u++)
                if (u == ul && ll == lane) d[u] = INFINITY;
        }
    }
    __syncthreads();

    // exact fp32 recheck: warp w -> candidate w
    {
        int p = s_cand[w];
        const float4* q4 = (const float4*)(xq + (size_t)row * KEYD);
        const float4* k4 = (const float4*)(ek + (size_t)p * KEYD);
        float s = 0.f;
        #pragma unroll
        for (int i = 0; i < 6; i++) {
            float4 qv = q4[lane + 32 * i];
            float4 kv = k4[lane + 32 * i];
            s += qv.x * kv.x + qv.y * kv.y + qv.z * kv.z + qv.w * kv.w;
        }
        #pragma unroll
        for (int off = 16; off; off >>= 1) s += __shfl_xor_sync(0xffffffffu, s, off);
        if (lane == 0) s_ex[w] = 1.0f - s * g_invq[row] * g_invk[p];
    }
    __syncthreads();

    if (t == 0) {
        bool used[TOP8];
        #pragma unroll
        for (int c = 0; c < TOP8; c++) used[c] = false;
        #pragma unroll
        for (int k = 0; k < TOPK; k++) {
            float best = INFINITY; int bi = 0x7fffffff; int slot = 0;
            #pragma unroll
            for (int c = 0; c < TOP8; c++) {
                if (!used[c] && (s_ex[c] < best || (s_ex[c] == best && s_cand[c] < bi))) {
                    best = s_ex[c]; bi = s_cand[c]; slot = c;
                }
            }
            used[slot] = true;
            s_sel[k] = bi;
            atomicAdd(&g_cnt[bi], 1);
        }
    }
    __syncthreads();

    // gather: 40 row-copies (20 Pk + 20 Pv), warp w does rows w, 8+w, ..., 32+w
    int p0 = s_sel[0], p1 = s_sel[1], p2 = s_sel[2], p3 = s_sel[3];
    #pragma unroll
    for (int j = 0; j < 5; j++) {
        int c = w + 8 * j;               // 0..39
        int isv = (c >= 20);             // 0 = Pk, 1 = Pv
        int rr20 = isv ? (c - 20) : c;   // dest row 0..19
        const float4* src;
        if (rr20 < 16) {
            int k  = rr20 >> 2;
            int rr = rr20 & 3;
            int p  = (k == 0) ? p0 : (k == 1) ? p1 : (k == 2) ? p2 : p3;
            src = (const float4*)(e_p + ((size_t)p * EPL + isv * 4 + rr) * EMB);
        } else {
            src = (const float4*)(g_p + ((size_t)(rr20 - 16) + isv * 4) * EMB);
        }
        float4* dst = (float4*)(out + (size_t)isv * PV_OFF
                                + ((size_t)row * PK_ROWS + rr20) * EMB);
        #pragma unroll
        for (int i = 0; i < 6; i++)
            __stcs(dst + lane + 32 * i, src[lane + 32 * i]);
    }

    // x_block passthrough (dst only 4B-aligned -> scalar streaming stores)
    {
        const float* s = xb + (size_t)row * EMB;
        float* d = out + XB_OFF + (size_t)row * EMB;
        #pragma unroll
        for (int i = 0; i < 3; i++)
            __stcs(d + t + 256 * i, s[t + 256 * i]);
    }
}

// ---------------- kernel 3: finish (counts + loss), 1 block ----------------
__global__ __launch_bounds__(512) void finish_kernel(float* __restrict__ out) {
    const int p = threadIdx.x;
    const int lane = p & 31;
    int c = g_cnt[p];
    out[CNT_OFF + p] = (float)c;
    float colsum = 0.f;
    #pragma unroll
    for (int by = 0; by < 32; by++) colsum += g_cpart[by * POOL + p];
    float local = colsum * (float)c;
    #pragma unroll
    for (int off = 16; off; off >>= 1)
        local += __shfl_xor_sync(0xffffffffu, local, off);
    __shared__ float s_w[16];
    if (lane == 0) s_w[p >> 5] = local;
    __syncthreads();
    if (p == 0) {
        float tot = 0.f;
        #pragma unroll
        for (int i = 0; i < 16; i++) tot += s_w[i];
        out[LOSS_OFF] = 1.0f - tot / ((float)B_ * (float)B_ * (float)TOPK);
    }
}

// ---------------- launch ----------------
extern "C" void kernel_launch(void* const* d_in, const int* in_sizes, int n_in,
                              void* d_out, int out_size) {
    const float* x_querry = (const float*)d_in[0];
    const float* x_block  = (const float*)d_in[1];
    const float* e_k      = (const float*)d_in[2];
    const float* e_p      = (const float*)d_in[3];
    const float* g_p      = (const float*)d_in[4];
    (void)in_sizes; (void)n_in; (void)out_size;

    float* out = (float*)d_out;
    float* d_C = nullptr;
    cudaGetSymbolAddress((void**)&d_C, g_C);

    gemm_tf32_kernel<<<dim3(POOL / BN, B_ / BM), 256>>>(x_querry, e_k, d_C);        // 1
    routegather_kernel<<<B_, 256>>>(d_C, x_querry, e_k, e_p, g_p, x_block, out);    // 2
    finish_kernel<<<1, 512>>>(out);                                                 // 3
}